// round 17
// baseline (speedup 1.0000x reference)
#include <cuda_runtime.h>
#include <math.h>

#define MAX_NODES 20000
#define MAX_EDGES 640000
#define SLOTS     160          // padded per-node edge capacity (max degree ~66)
#define TABN      8192
#define DMAX      2.0f
#define TSCALE    4095.5f      // (TABN-1)/DMAX
#define ROWF      96           // floats per table row: [F(32) | F@w_v(32) | F@w_d(32)]
#define ROWU2     24           // ulonglong2 per row

// Static scratch (no allocation allowed).
__device__ float  g_table[TABN * ROWF];            // fused lookup, 3MB (L2-hot)
__device__ int    g_count[MAX_NODES];
__device__ float4 g_slot_rs[MAX_NODES * SLOTS];    // per-slot payload (X,Y,Z,u)

// ---------------------------------------------------------------------------
// Packed f32x2 helpers (Blackwell — only reachable via PTX)
// ---------------------------------------------------------------------------
typedef unsigned long long u64;

__device__ __forceinline__ u64 pack2(float lo, float hi) {
    u64 r;
    asm("mov.b64 %0, {%1, %2};" : "=l"(r) : "f"(lo), "f"(hi));
    return r;
}
__device__ __forceinline__ void unpack2(u64 v, float& lo, float& hi) {
    asm("mov.b64 {%0, %1}, %2;" : "=f"(lo), "=f"(hi) : "l"(v));
}
#define FMA2(d, a, b, c) \
    asm("fma.rn.f32x2 %0, %1, %2, %3;" : "=l"(d) : "l"(a), "l"(b), "l"(c))
#define MUL2(d, a, b) \
    asm("mul.rn.f32x2 %0, %1, %2;" : "=l"(d) : "l"(a), "l"(b))
#define ADD2(d, a, b) \
    asm("add.rn.f32x2 %0, %1, %2;" : "=l"(d) : "l"(a), "l"(b))

__device__ __forceinline__ u64 shfl_xor64(u64 v, int m) {
    return __shfl_xor_sync(0xffffffffu, v, m);
}

// ---------------------------------------------------------------------------
// Per-edge prep: compute (X,Y,Z,u) and write it DIRECTLY into the node's
// slot list. u pre-clamped so the node kernel needs no idx clamp.
// ---------------------------------------------------------------------------
__global__ void prep_kernel(const float* __restrict__ r_ij,
                            const int* __restrict__ edges_src, int E) {
    int e = blockIdx.x * blockDim.x + threadIdx.x;
    if (e >= E) return;

    int n = edges_src[e];
    int slot = atomicAdd(&g_count[n], 1);

    float rx = r_ij[3 * e + 0];
    float ry = r_ij[3 * e + 1];
    float rz = r_ij[3 * e + 2];
    float d2 = rx * rx + ry * ry + rz * rz;
    float d  = sqrtf(d2);
    // rs = tens_sigmoid(r * 7): r*7 / sqrt(1 + 49*d2)
    float inv = rsqrtf(1.0f + 49.0f * d2) * 7.0f;
    float u = fminf(d * TSCALE, (float)(TABN - 1) - 0.5f);  // idx always <= TABN-2
    if (slot < SLOTS)
        g_slot_rs[n * SLOTS + slot] = make_float4(rx * inv, ry * inv, rz * inv, u);
}

// ---------------------------------------------------------------------------
// Table builder (also zeroes g_count — fused to save a launch).
// Row t = [F(d_t) | F@w_v | F@w_d], packed-f32x2 MLP + two 32x32 matvecs.
// ---------------------------------------------------------------------------
__global__ __launch_bounds__(128)
void table_kernel(const float* __restrict__ w_rad,  const float* __restrict__ b_rad,
                  const float* __restrict__ w_direct,
                  const float* __restrict__ w1, const float* __restrict__ b1,
                  const float* __restrict__ w2, const float* __restrict__ b2,
                  const float* __restrict__ w3, const float* __restrict__ b3,
                  const float* __restrict__ w_v, const float* __restrict__ w_d,
                  int N)
{
    __shared__ __align__(16) float s_wrad[8 * 32];
    __shared__ __align__(16) float s_brad[32];
    __shared__ __align__(16) float s_wdir[32 * 32];
    __shared__ __align__(16) float s_w1[32 * 64];
    __shared__ __align__(16) float s_b1[64];
    __shared__ __align__(16) float s_w2[64 * 64];
    __shared__ __align__(16) float s_b2[64];
    __shared__ __align__(16) float s_w3[64 * 32];
    __shared__ __align__(16) float s_b3[32];
    __shared__ __align__(16) float s_wv[32 * 32];
    __shared__ __align__(16) float s_wd[32 * 32];

    int t = blockIdx.x * blockDim.x + threadIdx.x;
    if (t < N) g_count[t] = 0;          // fused zeroing
    if (blockIdx.x * blockDim.x >= TABN) return;   // zero-only blocks

    for (int i = threadIdx.x; i < 8 * 32;  i += blockDim.x) s_wrad[i] = w_rad[i];
    for (int i = threadIdx.x; i < 32;      i += blockDim.x) s_brad[i] = b_rad[i];
    for (int i = threadIdx.x; i < 32 * 32; i += blockDim.x) s_wdir[i] = w_direct[i];
    for (int i = threadIdx.x; i < 32 * 64; i += blockDim.x) s_w1[i]   = w1[i];
    for (int i = threadIdx.x; i < 64;      i += blockDim.x) s_b1[i]   = b1[i];
    for (int i = threadIdx.x; i < 64 * 64; i += blockDim.x) s_w2[i]   = w2[i];
    for (int i = threadIdx.x; i < 64;      i += blockDim.x) s_b2[i]   = b2[i];
    for (int i = threadIdx.x; i < 64 * 32; i += blockDim.x) s_w3[i]   = w3[i];
    for (int i = threadIdx.x; i < 32;      i += blockDim.x) s_b3[i]   = b3[i];
    for (int i = threadIdx.x; i < 32 * 32; i += blockDim.x) s_wv[i]   = w_v[i];
    for (int i = threadIdx.x; i < 32 * 32; i += blockDim.x) s_wd[i]   = w_d[i];
    __syncthreads();

    if (t >= TABN) return;

    float d = (float)t * (DMAX / (float)(TABN - 1));

    // 8 Gaussian RBFs; centers k/7, width 1/8
    float enc[8];
    #pragma unroll
    for (int k = 0; k < 8; k++) {
        float x = (d - (float)k * (1.0f / 7.0f)) * 8.0f;
        enc[k] = __expf(-x * x);
    }

    const u64* W_RAD = (const u64*)s_wrad;
    const u64* B_RAD = (const u64*)s_brad;
    const u64* W_DIR = (const u64*)s_wdir;
    const u64* W_1   = (const u64*)s_w1;
    const u64* B_1   = (const u64*)s_b1;
    const u64* W_2   = (const u64*)s_w2;
    const u64* B_2   = (const u64*)s_b2;
    const u64* W_3   = (const u64*)s_w3;
    const u64* B_3   = (const u64*)s_b3;

    u64 h2[16];
    #pragma unroll
    for (int p = 0; p < 16; p++) h2[p] = B_RAD[p];
    #pragma unroll
    for (int k = 0; k < 8; k++) {
        u64 ek2 = pack2(enc[k], enc[k]);
        #pragma unroll
        for (int p = 0; p < 16; p++) FMA2(h2[p], ek2, W_RAD[k * 16 + p], h2[p]);
    }

    u64 rad2[16];
    #pragma unroll
    for (int p = 0; p < 16; p++) rad2[p] = 0;
    u64 t1[32];
    #pragma unroll
    for (int p = 0; p < 32; p++) t1[p] = B_1[p];

    #pragma unroll
    for (int kp = 0; kp < 16; kp++) {
        float hk0, hk1;
        unpack2(h2[kp], hk0, hk1);
        u64 a0 = pack2(hk0, hk0);
        u64 a1 = pack2(hk1, hk1);
        int k0 = 2 * kp, k1 = 2 * kp + 1;
        #pragma unroll
        for (int p = 0; p < 16; p++) {
            FMA2(rad2[p], a0, W_DIR[k0 * 16 + p], rad2[p]);
            FMA2(rad2[p], a1, W_DIR[k1 * 16 + p], rad2[p]);
        }
        #pragma unroll
        for (int p = 0; p < 32; p++) {
            FMA2(t1[p], a0, W_1[k0 * 32 + p], t1[p]);
            FMA2(t1[p], a1, W_1[k1 * 32 + p], t1[p]);
        }
    }
    #pragma unroll
    for (int p = 0; p < 32; p++) {
        float lo, hi;
        unpack2(t1[p], lo, hi);
        lo = fmaxf(lo, 0.1f * lo);
        hi = fmaxf(hi, 0.1f * hi);
        t1[p] = pack2(lo, hi);
    }

    u64 t2[32];
    #pragma unroll
    for (int p = 0; p < 32; p++) t2[p] = B_2[p];
    #pragma unroll
    for (int kp = 0; kp < 32; kp++) {
        float k0v, k1v;
        unpack2(t1[kp], k0v, k1v);
        u64 a0 = pack2(k0v, k0v);
        u64 a1 = pack2(k1v, k1v);
        int k0 = 2 * kp, k1 = 2 * kp + 1;
        #pragma unroll
        for (int p = 0; p < 32; p++) {
            FMA2(t2[p], a0, W_2[k0 * 32 + p], t2[p]);
            FMA2(t2[p], a1, W_2[k1 * 32 + p], t2[p]);
        }
    }
    #pragma unroll
    for (int p = 0; p < 32; p++) {
        float lo, hi;
        unpack2(t2[p], lo, hi);
        lo = fmaxf(lo, 0.1f * lo);
        hi = fmaxf(hi, 0.1f * hi);
        t2[p] = pack2(lo, hi);
    }

    u64 one2 = pack2(1.0f, 1.0f);
    #pragma unroll
    for (int p = 0; p < 16; p++) FMA2(rad2[p], one2, B_3[p], rad2[p]);
    #pragma unroll
    for (int kp = 0; kp < 32; kp++) {
        float k0v, k1v;
        unpack2(t2[kp], k0v, k1v);
        u64 a0 = pack2(k0v, k0v);
        u64 a1 = pack2(k1v, k1v);
        int k0 = 2 * kp, k1 = 2 * kp + 1;
        #pragma unroll
        for (int p = 0; p < 16; p++) {
            FMA2(rad2[p], a0, W_3[k0 * 16 + p], rad2[p]);
            FMA2(rad2[p], a1, W_3[k1 * 16 + p], rad2[p]);
        }
    }

    ulonglong2* dst = (ulonglong2*)(g_table + (size_t)t * ROWF);

    // F section
    #pragma unroll
    for (int q = 0; q < 8; q++)
        dst[q] = make_ulonglong2(rad2[2 * q], rad2[2 * q + 1]);

    // unpack F to scalars
    float f[32];
    #pragma unroll
    for (int p = 0; p < 16; p++) unpack2(rad2[p], f[2 * p], f[2 * p + 1]);

    // Tv = F @ w_v  (Tv[v] = sum_a f[a] * w_v[a*32+v])
    {
        u64 tv[16];
        #pragma unroll
        for (int p = 0; p < 16; p++) tv[p] = 0;
        #pragma unroll
        for (int a = 0; a < 32; a++) {
            u64 fa2 = pack2(f[a], f[a]);
            const u64* Wrow = (const u64*)(s_wv + a * 32);
            #pragma unroll
            for (int p = 0; p < 16; p++) FMA2(tv[p], fa2, Wrow[p], tv[p]);
        }
        #pragma unroll
        for (int q = 0; q < 8; q++)
            dst[8 + q] = make_ulonglong2(tv[2 * q], tv[2 * q + 1]);
    }

    // Td = F @ w_d
    {
        u64 td[16];
        #pragma unroll
        for (int p = 0; p < 16; p++) td[p] = 0;
        #pragma unroll
        for (int a = 0; a < 32; a++) {
            u64 fa2 = pack2(f[a], f[a]);
            const u64* Wrow = (const u64*)(s_wd + a * 32);
            #pragma unroll
            for (int p = 0; p < 16; p++) FMA2(td[p], fa2, Wrow[p], td[p]);
        }
        #pragma unroll
        for (int q = 0; q < 8; q++)
            dst[16 + q] = make_ulonglong2(td[2 * q], td[2 * q + 1]);
    }
}

// ---------------------------------------------------------------------------
// Fused per-node kernel. One warp per node; warp = 4 edge groups x 8 channel
// lanes; per step 4 edges in flight. Table rows carry pre-contracted
// [F | F@w_v | F@w_d], so outputs accumulate directly in final channel
// space: epilogue = group-reduce + stores. NO shared memory at all.
// ---------------------------------------------------------------------------
__global__ __launch_bounds__(128)
void node_kernel(float* __restrict__ out, int N)
{
    int lane = threadIdx.x & 31;
    int g = lane >> 3;      // edge group 0..3
    int l = lane & 7;       // channel quarter 0..7 (channels l*4 .. l*4+3)
    int n = blockIdx.x * 4 + (threadIdx.x >> 5);
    if (n >= N) return;

    const float4* srs = g_slot_rs + (size_t)n * SLOTS;
    const ulonglong2* tab = (const ulonglong2*)g_table;   // ROWU2 per row
    int cnt = g_count[n];
    if (cnt > SLOTS) cnt = SLOTS;

    // accumulators, all packed channel pairs (p=0: ch 4l,4l+1; p=1: 4l+2,4l+3)
    u64 aa2[2];                 // A_a
    u64 av2[3][2];              // out_v  (x,y,z)
    u64 ad2[6][2];              // out_d  (XX,YY,ZZ,XY,XZ,YZ)
    aa2[0] = aa2[1] = 0;
    #pragma unroll
    for (int c = 0; c < 3; c++) av2[c][0] = av2[c][1] = 0;
    #pragma unroll
    for (int m = 0; m < 6; m++) ad2[m][0] = ad2[m][1] = 0;

    for (int t0 = 0; t0 < cnt; t0 += 32) {
        float4 myrs = (t0 + lane < cnt) ? __ldg(&srs[t0 + lane])
                                        : make_float4(0.f, 0.f, 0.f, 0.f);
        int rem = cnt - t0; if (rem > 32) rem = 32;
        int steps = (rem + 3) >> 2;

        #pragma unroll 4
        for (int i = 0; i < steps; i++) {
            int j = i * 4 + g;
            float u = __shfl_sync(0xffffffffu, myrs.w, j);
            float X = __shfl_sync(0xffffffffu, myrs.x, j);
            float Y = __shfl_sync(0xffffffffu, myrs.y, j);
            float Z = __shfl_sync(0xffffffffu, myrs.z, j);
            float wgt = (j < rem) ? 1.0f : 0.0f;   // padded lanes: zeros anyway

            int idx = (int)u;
            float frac = u - (float)idx;
            const ulonglong2* rp = tab + (size_t)idx * ROWU2 + l;
            ulonglong2 F0 = __ldg(rp);            // F pairs
            ulonglong2 F1 = __ldg(rp + ROWU2);
            ulonglong2 V0 = __ldg(rp + 8);        // F@w_v pairs
            ulonglong2 V1 = __ldg(rp + 8 + ROWU2);
            ulonglong2 D0 = __ldg(rp + 16);       // F@w_d pairs
            ulonglong2 D1 = __ldg(rp + 16 + ROWU2);

            float frw = frac * wgt;
            float omw = (1.0f - frac) * wgt;
            u64 fr2 = pack2(frw, frw);
            u64 om2 = pack2(omw, omw);
            u64 X2 = pack2(X, X), Y2 = pack2(Y, Y), Z2 = pack2(Z, Z);

            u64 ta, tb;
            u64 fa, fb, va, vb, da, db;
            MUL2(ta, F1.x, fr2);  FMA2(fa, F0.x, om2, ta);
            MUL2(tb, F1.y, fr2);  FMA2(fb, F0.y, om2, tb);
            MUL2(ta, V1.x, fr2);  FMA2(va, V0.x, om2, ta);
            MUL2(tb, V1.y, fr2);  FMA2(vb, V0.y, om2, tb);
            MUL2(ta, D1.x, fr2);  FMA2(da, D0.x, om2, ta);
            MUL2(tb, D1.y, fr2);  FMA2(db, D0.y, om2, tb);

            // aa += F
            ADD2(aa2[0], aa2[0], fa);
            ADD2(aa2[1], aa2[1], fb);
            // av += (F@w_v) * rs
            FMA2(av2[0][0], va, X2, av2[0][0]);  FMA2(av2[0][1], vb, X2, av2[0][1]);
            FMA2(av2[1][0], va, Y2, av2[1][0]);  FMA2(av2[1][1], vb, Y2, av2[1][1]);
            FMA2(av2[2][0], va, Z2, av2[2][0]);  FMA2(av2[2][1], vb, Z2, av2[2][1]);
            // ad += (F@w_d) * rs_i rs_j
            u64 mXX, mYY, mZZ, mXY, mXZ, mYZ;
            MUL2(mXX, X2, X2); MUL2(mYY, Y2, Y2); MUL2(mZZ, Z2, Z2);
            MUL2(mXY, X2, Y2); MUL2(mXZ, X2, Z2); MUL2(mYZ, Y2, Z2);
            FMA2(ad2[0][0], da, mXX, ad2[0][0]); FMA2(ad2[0][1], db, mXX, ad2[0][1]);
            FMA2(ad2[1][0], da, mYY, ad2[1][0]); FMA2(ad2[1][1], db, mYY, ad2[1][1]);
            FMA2(ad2[2][0], da, mZZ, ad2[2][0]); FMA2(ad2[2][1], db, mZZ, ad2[2][1]);
            FMA2(ad2[3][0], da, mXY, ad2[3][0]); FMA2(ad2[3][1], db, mXY, ad2[3][1]);
            FMA2(ad2[4][0], da, mXZ, ad2[4][0]); FMA2(ad2[4][1], db, mXZ, ad2[4][1]);
            FMA2(ad2[5][0], da, mYZ, ad2[5][0]); FMA2(ad2[5][1], db, mYZ, ad2[5][1]);
        }
    }

    // reduce across the 4 edge groups (64-bit shuffles)
    #pragma unroll
    for (int p = 0; p < 2; p++) {
        ADD2(aa2[p], aa2[p], shfl_xor64(aa2[p], 8));
        ADD2(aa2[p], aa2[p], shfl_xor64(aa2[p], 16));
        #pragma unroll
        for (int c = 0; c < 3; c++) {
            ADD2(av2[c][p], av2[c][p], shfl_xor64(av2[c][p], 8));
            ADD2(av2[c][p], av2[c][p], shfl_xor64(av2[c][p], 16));
        }
        #pragma unroll
        for (int m = 0; m < 6; m++) {
            ADD2(ad2[m][p], ad2[m][p], shfl_xor64(ad2[m][p], 8));
            ADD2(ad2[m][p], ad2[m][p], shfl_xor64(ad2[m][p], 16));
        }
    }

    if (g != 0) return;

    // ---- stores: everything is contiguous per lane ----
    // A_a: out[n*32 + 4l .. 4l+3]
    {
        float a0, a1, a2, a3;
        unpack2(aa2[0], a0, a1);
        unpack2(aa2[1], a2, a3);
        *(float4*)(out + (size_t)n * 32 + l * 4) = make_float4(a0, a1, a2, a3);
    }

    // out_v: [N][32][3] at offset N*32; lane covers channels 4l..4l+3 -> 12 floats
    {
        float vx0, vx1, vx2, vx3, vy0, vy1, vy2, vy3, vz0, vz1, vz2, vz3;
        unpack2(av2[0][0], vx0, vx1); unpack2(av2[0][1], vx2, vx3);
        unpack2(av2[1][0], vy0, vy1); unpack2(av2[1][1], vy2, vy3);
        unpack2(av2[2][0], vz0, vz1); unpack2(av2[2][1], vz2, vz3);
        float* pv = out + (size_t)N * 32 + (size_t)n * 96 + l * 12;
        ((float4*)pv)[0] = make_float4(vx0, vy0, vz0, vx1);
        ((float4*)pv)[1] = make_float4(vy1, vz1, vx2, vy2);
        ((float4*)pv)[2] = make_float4(vz2, vx3, vy3, vz3);
    }

    // out_d: [N][32][3][3] at offset N*128; lane covers 4 channels -> 36 floats
    {
        float xx[4], yy[4], zz[4], xy[4], xz[4], yz[4];
        unpack2(ad2[0][0], xx[0], xx[1]); unpack2(ad2[0][1], xx[2], xx[3]);
        unpack2(ad2[1][0], yy[0], yy[1]); unpack2(ad2[1][1], yy[2], yy[3]);
        unpack2(ad2[2][0], zz[0], zz[1]); unpack2(ad2[2][1], zz[2], zz[3]);
        unpack2(ad2[3][0], xy[0], xy[1]); unpack2(ad2[3][1], xy[2], xy[3]);
        unpack2(ad2[4][0], xz[0], xz[1]); unpack2(ad2[4][1], xz[2], xz[3]);
        unpack2(ad2[5][0], yz[0], yz[1]); unpack2(ad2[5][1], yz[2], yz[3]);
        float* pd = out + (size_t)N * 128 + (size_t)n * 288 + l * 36;
        #pragma unroll
        for (int c = 0; c < 4; c++) {
            float* q = pd + c * 9;
            // row-major 3x3: [XX XY XZ / XY YY YZ / XZ YZ ZZ]
            q[0] = xx[c]; q[1] = xy[c]; q[2] = xz[c];
            q[3] = xy[c]; q[4] = yy[c]; q[5] = yz[c];
            q[6] = xz[c]; q[7] = yz[c]; q[8] = zz[c];
        }
    }
}

// ---------------------------------------------------------------------------
// kernel_launch — 3 kernels: table(+zero) -> prep -> node
// ---------------------------------------------------------------------------
extern "C" void kernel_launch(void* const* d_in, const int* in_sizes, int n_in,
                              void* d_out, int out_size) {
    const float* r_ij     = (const float*)d_in[0];
    const float* w_rad    = (const float*)d_in[1];
    const float* b_rad    = (const float*)d_in[2];
    const float* w_direct = (const float*)d_in[3];
    const float* w1       = (const float*)d_in[4];
    const float* b1       = (const float*)d_in[5];
    const float* w2       = (const float*)d_in[6];
    const float* b2       = (const float*)d_in[7];
    const float* w3       = (const float*)d_in[8];
    const float* b3       = (const float*)d_in[9];
    const float* w_v      = (const float*)d_in[10];
    const float* w_d      = (const float*)d_in[11];
    const int*   e_src    = (const int*)  d_in[12];

    int E = in_sizes[0] / 3;
    int N = out_size / 416;

    float* out = (float*)d_out;

    // Table build (F | F@w_v | F@w_d) + fused g_count zeroing
    int span = (TABN > N) ? TABN : N;
    table_kernel<<<(span + 127) / 128, 128>>>(
        w_rad, b_rad, w_direct, w1, b1, w2, b2, w3, b3, w_v, w_d, N);

    // Per-edge prep: payload (X,Y,Z,u) written straight into node slots
    prep_kernel<<<(E + 255) / 256, 256>>>(r_ij, e_src, E);

    // Fused gather + table interp + direct-output accumulation
    node_kernel<<<(N + 3) / 4, 128>>>(out, N);
}